// round 15
// baseline (speedup 1.0000x reference)
#include <cuda_runtime.h>
#include <cuda_fp16.h>

// Problem constants
#define FT_B 4
#define FT_C 256
#define FT_T 16
#define FT_H 64
#define FT_W 64
#define SPATIAL (FT_T*FT_H*FT_W)          // 65536 per (b,c)
#define FT_PER_B ((size_t)SPATIAL*FT_C)   // 16,777,216 elements per batch in fT

#define CG 64                              // channels per block (32 lanes x 2ch)

// Channels-last fp16 scratch: fT[b][t][h][w][c]  (134 MB static device array)
__device__ __half g_fT[(size_t)FT_B * FT_T * FT_H * FT_W * FT_C];

// named-barrier helpers (producer: arrive, non-blocking; consumer: sync)
#define NB_ARRIVE(id, cnt) asm volatile("bar.arrive %0, %1;" :: "r"(id), "r"(cnt) : "memory")
#define NB_SYNC(id, cnt)   asm volatile("bar.sync %0, %1;"   :: "r"(id), "r"(cnt) : "memory")

// ---------------------------------------------------------------------------
// Kernel 1: transpose (B,C,THW) f32 -> (B,THW,C) f16.
// 64x64 tiles; smem half tile with pitch 65 (conflict-free column reads);
// half2 STG (128 B/warp fully coalesced). DRAM-bound at ~6.3 TB/s; leave it.
// ---------------------------------------------------------------------------
__global__ __launch_bounds__(256, 6)
void transpose_kernel(const float* __restrict__ f) {
    __shared__ __half tile[64][65];
    const int b  = blockIdx.z;
    const int s0 = blockIdx.x * 64;   // spatial base
    const int c0 = blockIdx.y * 64;   // channel base
    const int tid = threadIdx.x;
    const int sx  = tid & 63;         // spatial within tile (coalesced reads)
    const int cyb = tid >> 6;         // 0..3

    const float* src = f + (size_t)b * FT_C * SPATIAL + s0 + sx;
    #pragma unroll
    for (int j = 0; j < 16; ++j) {
        int cy = cyb + j * 4;
        tile[cy][sx] = __float2half(src[(size_t)(c0 + cy) * SPATIAL]);
    }
    __syncthreads();

    // write: lane l covers channels 2l,2l+1; warp w handles 8 spatial rows
    const int l = tid & 31;
    const int w = tid >> 5;
    __half* dst = g_fT + (size_t)b * SPATIAL * FT_C + c0 + 2 * l;
    #pragma unroll
    for (int j = 0; j < 8; ++j) {
        int s = w + j * 8;
        __half2 v = __halves2half2(tile[2 * l][s], tile[2 * l + 1][s]);
        *reinterpret_cast<__half2*>(dst + (size_t)(s0 + s) * FT_C) = v;
    }
}

// ---------------------------------------------------------------------------
// Kernel 2: fused RoIAlign3D + avg_pool3d(k=2,s=1).
// Block = 8 warps x 32 lanes. warp = y-sample row, lane = channel PAIR
// (half2 gathers -> fp32 immediately; ALL math scalar fp32 -- proven loop;
// packed half2 and packed f32x2 variants both regressed, do not revisit).
// Addressing: four 64-bit corner POINTERS (32-bit combined offsets cost
// ~17 pts of ALU). Interp: corner-major, 10 FFMA/channel.
// grid = (n_rois, 4): roi fastest -> resident blocks share one 64-channel
// slice (L2 resident). 6 CTAs/SM.
// BARRIER DIET (this round): srows exchange uses PAIRWISE named barriers
// (warp w consumes only warp w+1's row); staging is TRIPLE-buffered so
// stream-out emits plane ts-2 (reads buffers disjoint from this iter's
// write) and runs BEFORE the pairwise bar; ONE full __syncthreads per
// iteration (at the end) covers all WAR hazards.
// ---------------------------------------------------------------------------
struct __align__(16) AxisEntry { int o0; int o1; float w0; float w1; };

__device__ __forceinline__ void stream_out_plane(
    float* __restrict__ out, int r, int c0, int to,
    const __half* sA, const __half* sB, int tid)
{
    const size_t obase = ((size_t)r * FT_C + c0) * 196 + (size_t)to * 49;
    // 3136 = 12*256 + 64 : branch-free body + small tail
    #pragma unroll
    for (int k = 0; k < 12; ++k) {
        int idx = tid + k * 256;
        int cc  = idx / 49;
        int pix = idx - cc * 49;
        float v = (__half2float(sA[pix * 66 + cc]) +
                   __half2float(sB[pix * 66 + cc])) * 0.125f;
        __stcs(&out[obase + (size_t)cc * 196 + pix], v);
    }
    if (tid < 64) {
        int idx = tid + 12 * 256;
        int cc  = idx / 49;
        int pix = idx - cc * 49;
        float v = (__half2float(sA[pix * 66 + cc]) +
                   __half2float(sB[pix * 66 + cc])) * 0.125f;
        __stcs(&out[obase + (size_t)cc * 196 + pix], v);
    }
}

__global__ __launch_bounds__(256, 6)
void roialign_pool_kernel(const float* __restrict__ rois,
                          float* __restrict__ out) {
    __shared__ AxisEntry sT[5], sY[8], sX[8];
    __shared__ float2  srows[8][7][32];       // [ysample][xout][lane]  14336 B
    __shared__ __half2 staging3[3][49][33];   // [buf][pix][lanepair]   19404 B

    const int r   = blockIdx.x;             // roi (fastest-varying)
    const int g   = blockIdx.y;             // channel group 0..3
    const int tid = threadIdx.x;
    const int w   = tid >> 5;               // warp id = y-sample row
    const int l   = tid & 31;               // lane    = channel pair
    const float* roi = rois + r * 7;

    // --- axis sample tables (matches reference _axis_samples) ---
    if (tid < 21) {
        float start, end, fsize; int n, k, stride; AxisEntry* dstE;
        if (tid < 5)       { k = tid;      start = roi[5];          end = roi[6];          fsize = (float)FT_T; n = 5; stride = FT_H*FT_W*FT_C; dstE = &sT[k]; }
        else if (tid < 13) { k = tid - 5;  start = roi[2]*0.0625f;  end = roi[4]*0.0625f;  fsize = (float)FT_H; n = 8; stride = FT_W*FT_C;      dstE = &sY[k]; }
        else               { k = tid - 13; start = roi[1]*0.0625f;  end = roi[3]*0.0625f;  fsize = (float)FT_W; n = 8; stride = FT_C;           dstE = &sX[k]; }
        float length = fmaxf(end - start + 1.0f, 1.0f);
        float step   = length / (float)(n - 1);
        float coord  = start + step * (float)k;
        float valid  = (coord >= 0.0f && coord < fsize) ? 1.0f : 0.0f;
        float lo     = floorf(coord);
        lo = fminf(fmaxf(lo, 0.0f), fsize - 1.0f);
        float frac   = coord - lo;
        int loi = (int)lo;
        int hii = min(loi + 1, (int)fsize - 1);
        dstE->o0 = loi * stride;
        dstE->o1 = hii * stride;
        dstE->w0 = (1.0f - frac) * valid;
        dstE->w1 = frac * valid;
    }
    __syncthreads();

    const int b  = (int)roi[0];
    const int c0 = g * CG;
    const __half* bp = g_fT + (size_t)b * FT_PER_B + c0 + 2 * l;

    // this warp's y entry (fixed for all t)
    const int4  y4  = *reinterpret_cast<const int4*>(&sY[w]);
    const int   yO0 = y4.x, yO1 = y4.y;
    const float yW0 = __int_as_float(y4.z), yW1 = __int_as_float(y4.w);

    int bufc = 0;                  // ts % 3 (current write buffer)
    for (int ts = 0; ts < 5; ++ts) {
        const int4  t4  = *reinterpret_cast<const int4*>(&sT[ts]);
        const int   tO0 = t4.x, tO1 = t4.y;
        const float tW0 = __int_as_float(t4.z), tW1 = __int_as_float(t4.w);

        // four 64-bit corner pointers (proven addressing -- keep!)
        const __half* p00 = bp + tO0 + yO0;
        const __half* p01 = bp + tO0 + yO1;
        const __half* p10 = bp + tO1 + yO0;
        const __half* p11 = bp + tO1 + yO1;
        const float w00 = tW0 * yW0, w01 = tW0 * yW1;
        const float w10 = tW1 * yW0, w11 = tW1 * yW1;

        // gather + fp32 interp (corner-major, 10 FFMA/ch) + x-pool -> srows
        float2 vprev;
        #pragma unroll
        for (int xs = 0; xs < 8; ++xs) {
            const int4  x4  = *reinterpret_cast<const int4*>(&sX[xs]);
            const int   xO0 = x4.x, xO1 = x4.y;
            const float xW0 = __int_as_float(x4.z), xW1 = __int_as_float(x4.w);

            float2 a0 = __half22float2(__ldg(reinterpret_cast<const __half2*>(p00 + xO0)));
            float2 a1 = __half22float2(__ldg(reinterpret_cast<const __half2*>(p00 + xO1)));
            float2 b0 = __half22float2(__ldg(reinterpret_cast<const __half2*>(p01 + xO0)));
            float2 b1 = __half22float2(__ldg(reinterpret_cast<const __half2*>(p01 + xO1)));
            float2 c0v = __half22float2(__ldg(reinterpret_cast<const __half2*>(p10 + xO0)));
            float2 c1v = __half22float2(__ldg(reinterpret_cast<const __half2*>(p10 + xO1)));
            float2 d0 = __half22float2(__ldg(reinterpret_cast<const __half2*>(p11 + xO0)));
            float2 d1 = __half22float2(__ldg(reinterpret_cast<const __half2*>(p11 + xO1)));

            // corner-major bilinear-in-(t,y), then lerp in x: 10 FFMA/channel
            float e0x = w00 * a0.x + w01 * b0.x + w10 * c0v.x + w11 * d0.x;
            float e1x = w00 * a1.x + w01 * b1.x + w10 * c1v.x + w11 * d1.x;
            float e0y = w00 * a0.y + w01 * b0.y + w10 * c0v.y + w11 * d0.y;
            float e1y = w00 * a1.y + w01 * b1.y + w10 * c1v.y + w11 * d1.y;

            float2 v;
            v.x = xW0 * e0x + xW1 * e1x;
            v.y = xW0 * e0y + xW1 * e1y;

            if (xs > 0) {
                float2 rp;
                rp.x = vprev.x + v.x;
                rp.y = vprev.y + v.y;
                srows[w][xs - 1][l] = rp;     // stream out, don't persist
            }
            vprev = v;
        }

        // stream-out plane (ts-2): reads buffers (ts-2)%3 and (ts-1)%3 --
        // both written before the last full barrier, disjoint from this
        // iteration's write buffer. Overlaps with the pairwise bar below.
        if (ts >= 2) {
            int bA = ts - 2 - ((ts - 2) / 3) * 3;   // (ts-2)%3
            int bB = ts - 1 - ((ts - 1) / 3) * 3;   // (ts-1)%3
            stream_out_plane(out, r, c0, ts - 2,
                             reinterpret_cast<const __half*>(staging3[bA]),
                             reinterpret_cast<const __half*>(staging3[bB]), tid);
        }

        // pairwise producer->consumer sync on srows (barrier id k = warps {k-1,k})
        if (w > 0) NB_ARRIVE(w, 64);       // I published srows[w]
        if (w < 7) NB_SYNC(w + 1, 64);     // wait for srows[w+1]

        // y-pool using own regs... (rp streamed; re-read own row from smem)
        if (w < 7) {
            #pragma unroll
            for (int xo = 0; xo < 7; ++xo) {
                float2 a  = srows[w][xo][l];
                float2 nb = srows[w + 1][xo][l];
                staging3[bufc][w * 7 + xo][l] =
                    __floats2half2_rn(a.x + nb.x, a.y + nb.y);
            }
        }

        __syncthreads();   // ONE full barrier per iteration: publishes
                           // staging3[bufc], closes srows + buffer WAR windows
        if (++bufc == 3) bufc = 0;
    }

    // epilogue: plane 3 = unscaled[3] (buf 0) + unscaled[4] (buf 1)
    stream_out_plane(out, r, c0, 3,
                     reinterpret_cast<const __half*>(staging3[0]),
                     reinterpret_cast<const __half*>(staging3[1]), tid);
}

// ---------------------------------------------------------------------------
extern "C" void kernel_launch(void* const* d_in, const int* in_sizes, int n_in,
                              void* d_out, int out_size) {
    const float* features = (const float*)d_in[0];
    const float* rois     = (const float*)d_in[1];
    float* out            = (float*)d_out;
    const int n_rois = in_sizes[1] / 7;

    dim3 tg(SPATIAL / 64, FT_C / 64, FT_B);
    transpose_kernel<<<tg, 256>>>(features);

    roialign_pool_kernel<<<dim3(n_rois, FT_C / CG), 256>>>(rois, out);
}

// round 16
// speedup vs baseline: 1.1795x; 1.1795x over previous
#include <cuda_runtime.h>
#include <cuda_fp16.h>

// Problem constants
#define FT_B 4
#define FT_C 256
#define FT_T 16
#define FT_H 64
#define FT_W 64
#define SPATIAL (FT_T*FT_H*FT_W)          // 65536 per (b,c)
#define FT_PER_B ((size_t)SPATIAL*FT_C)   // 16,777,216 elements per batch in fT

#define CG 64                              // channels per block (32 lanes x 2ch)

// Channels-last fp16 scratch: fT[b][t][h][w][c]  (134 MB static device array)
__device__ __half g_fT[(size_t)FT_B * FT_T * FT_H * FT_W * FT_C];

// ---------------------------------------------------------------------------
// Kernel 1: transpose (B,C,THW) f32 -> (B,THW,C) f16.
// 64x64 tiles; smem half tile with pitch 65 (conflict-free column reads);
// half2 STG (128 B/warp fully coalesced). Near DRAM roofline; leave it.
// ---------------------------------------------------------------------------
__global__ __launch_bounds__(256, 6)
void transpose_kernel(const float* __restrict__ f) {
    __shared__ __half tile[64][65];
    const int b  = blockIdx.z;
    const int s0 = blockIdx.x * 64;   // spatial base
    const int c0 = blockIdx.y * 64;   // channel base
    const int tid = threadIdx.x;
    const int sx  = tid & 63;         // spatial within tile (coalesced reads)
    const int cyb = tid >> 6;         // 0..3

    const float* src = f + (size_t)b * FT_C * SPATIAL + s0 + sx;
    #pragma unroll
    for (int j = 0; j < 16; ++j) {
        int cy = cyb + j * 4;
        tile[cy][sx] = __float2half(src[(size_t)(c0 + cy) * SPATIAL]);
    }
    __syncthreads();

    // write: lane l covers channels 2l,2l+1; warp w handles 8 spatial rows
    const int l = tid & 31;
    const int w = tid >> 5;
    __half* dst = g_fT + (size_t)b * SPATIAL * FT_C + c0 + 2 * l;
    #pragma unroll
    for (int j = 0; j < 8; ++j) {
        int s = w + j * 8;
        __half2 v = __halves2half2(tile[2 * l][s], tile[2 * l + 1][s]);
        *reinterpret_cast<__half2*>(dst + (size_t)(s0 + s) * FT_C) = v;
    }
}

// ---------------------------------------------------------------------------
// Kernel 2: fused RoIAlign3D + avg_pool3d(k=2,s=1).
// Block = 8 warps x 32 lanes. warp = y-sample row, lane = channel PAIR
// (half2 gathers -> fp32 immediately; ALL math scalar fp32 -- proven loop;
// packed half2 / packed f32x2 / named barriers all regressed: banned).
// Addressing: four 64-bit corner POINTERS (32-bit combined offsets cost
// ~17 pts of ALU). Interp: corner-major, 10 FFMA/channel.
// grid = (n_rois, 4): roi fastest -> resident blocks share one 64-channel
// slice (L2 resident). 6 CTAs/SM, regs ~40, TWO plain __syncthreads/iter.
// THIS ROUND: staging triple-buffered; stream-out of plane ts-2 runs
// BEFORE barrier 1 (fills barrier-skew window with useful store work).
// ---------------------------------------------------------------------------
struct __align__(16) AxisEntry { int o0; int o1; float w0; float w1; };

__device__ __forceinline__ void stream_out_plane(
    float* __restrict__ out, int r, int c0, int to,
    const __half* sA, const __half* sB, int tid)
{
    const size_t obase = ((size_t)r * FT_C + c0) * 196 + (size_t)to * 49;
    // 3136 = 12*256 + 64 : branch-free body + small tail
    #pragma unroll
    for (int k = 0; k < 12; ++k) {
        int idx = tid + k * 256;
        int cc  = idx / 49;
        int pix = idx - cc * 49;
        float v = (__half2float(sA[pix * 66 + cc]) +
                   __half2float(sB[pix * 66 + cc])) * 0.125f;
        __stcs(&out[obase + (size_t)cc * 196 + pix], v);
    }
    if (tid < 64) {
        int idx = tid + 12 * 256;
        int cc  = idx / 49;
        int pix = idx - cc * 49;
        float v = (__half2float(sA[pix * 66 + cc]) +
                   __half2float(sB[pix * 66 + cc])) * 0.125f;
        __stcs(&out[obase + (size_t)cc * 196 + pix], v);
    }
}

__global__ __launch_bounds__(256, 6)
void roialign_pool_kernel(const float* __restrict__ rois,
                          float* __restrict__ out) {
    __shared__ AxisEntry sT[5], sY[8], sX[8];
    __shared__ float2  srows[8][7][32];       // [ysample][xout][lane]  14336 B
    __shared__ __half2 staging3[3][49][33];   // [buf][pix][lanepair]   19404 B

    const int r   = blockIdx.x;             // roi (fastest-varying)
    const int g   = blockIdx.y;             // channel group 0..3
    const int tid = threadIdx.x;
    const int w   = tid >> 5;               // warp id = y-sample row
    const int l   = tid & 31;               // lane    = channel pair
    const float* roi = rois + r * 7;

    // --- axis sample tables (matches reference _axis_samples) ---
    if (tid < 21) {
        float start, end, fsize; int n, k, stride; AxisEntry* dstE;
        if (tid < 5)       { k = tid;      start = roi[5];          end = roi[6];          fsize = (float)FT_T; n = 5; stride = FT_H*FT_W*FT_C; dstE = &sT[k]; }
        else if (tid < 13) { k = tid - 5;  start = roi[2]*0.0625f;  end = roi[4]*0.0625f;  fsize = (float)FT_H; n = 8; stride = FT_W*FT_C;      dstE = &sY[k]; }
        else               { k = tid - 13; start = roi[1]*0.0625f;  end = roi[3]*0.0625f;  fsize = (float)FT_W; n = 8; stride = FT_C;           dstE = &sX[k]; }
        float length = fmaxf(end - start + 1.0f, 1.0f);
        float step   = length / (float)(n - 1);
        float coord  = start + step * (float)k;
        float valid  = (coord >= 0.0f && coord < fsize) ? 1.0f : 0.0f;
        float lo     = floorf(coord);
        lo = fminf(fmaxf(lo, 0.0f), fsize - 1.0f);
        float frac   = coord - lo;
        int loi = (int)lo;
        int hii = min(loi + 1, (int)fsize - 1);
        dstE->o0 = loi * stride;
        dstE->o1 = hii * stride;
        dstE->w0 = (1.0f - frac) * valid;
        dstE->w1 = frac * valid;
    }
    __syncthreads();

    const int b  = (int)roi[0];
    const int c0 = g * CG;
    const __half* bp = g_fT + (size_t)b * FT_PER_B + c0 + 2 * l;

    // this warp's y entry (fixed for all t)
    const int4  y4  = *reinterpret_cast<const int4*>(&sY[w]);
    const int   yO0 = y4.x, yO1 = y4.y;
    const float yW0 = __int_as_float(y4.z), yW1 = __int_as_float(y4.w);

    int bufc = 0;                  // ts % 3 (current write buffer)
    for (int ts = 0; ts < 5; ++ts) {
        const int4  t4  = *reinterpret_cast<const int4*>(&sT[ts]);
        const int   tO0 = t4.x, tO1 = t4.y;
        const float tW0 = __int_as_float(t4.z), tW1 = __int_as_float(t4.w);

        // four 64-bit corner pointers (proven addressing -- keep!)
        const __half* p00 = bp + tO0 + yO0;
        const __half* p01 = bp + tO0 + yO1;
        const __half* p10 = bp + tO1 + yO0;
        const __half* p11 = bp + tO1 + yO1;
        const float w00 = tW0 * yW0, w01 = tW0 * yW1;
        const float w10 = tW1 * yW0, w11 = tW1 * yW1;

        // gather + fp32 interp (corner-major, 10 FFMA/ch) + x-pool -> srows
        float2 vprev;
        #pragma unroll
        for (int xs = 0; xs < 8; ++xs) {
            const int4  x4  = *reinterpret_cast<const int4*>(&sX[xs]);
            const int   xO0 = x4.x, xO1 = x4.y;
            const float xW0 = __int_as_float(x4.z), xW1 = __int_as_float(x4.w);

            float2 a0 = __half22float2(__ldg(reinterpret_cast<const __half2*>(p00 + xO0)));
            float2 a1 = __half22float2(__ldg(reinterpret_cast<const __half2*>(p00 + xO1)));
            float2 b0 = __half22float2(__ldg(reinterpret_cast<const __half2*>(p01 + xO0)));
            float2 b1 = __half22float2(__ldg(reinterpret_cast<const __half2*>(p01 + xO1)));
            float2 c0v = __half22float2(__ldg(reinterpret_cast<const __half2*>(p10 + xO0)));
            float2 c1v = __half22float2(__ldg(reinterpret_cast<const __half2*>(p10 + xO1)));
            float2 d0 = __half22float2(__ldg(reinterpret_cast<const __half2*>(p11 + xO0)));
            float2 d1 = __half22float2(__ldg(reinterpret_cast<const __half2*>(p11 + xO1)));

            // corner-major bilinear-in-(t,y), then lerp in x: 10 FFMA/channel
            float e0x = w00 * a0.x + w01 * b0.x + w10 * c0v.x + w11 * d0.x;
            float e1x = w00 * a1.x + w01 * b1.x + w10 * c1v.x + w11 * d1.x;
            float e0y = w00 * a0.y + w01 * b0.y + w10 * c0v.y + w11 * d0.y;
            float e1y = w00 * a1.y + w01 * b1.y + w10 * c1v.y + w11 * d1.y;

            float2 v;
            v.x = xW0 * e0x + xW1 * e1x;
            v.y = xW0 * e0y + xW1 * e1y;

            if (xs > 0) {
                float2 rp;
                rp.x = vprev.x + v.x;
                rp.y = vprev.y + v.y;
                srows[w][xs - 1][l] = rp;     // stream out, don't persist
            }
            vprev = v;
        }

        // EARLY stream-out of plane (ts-2): buffers (ts-2)%3 and (ts-1)%3,
        // both published >= 1 full barrier ago; disjoint from this iter's
        // write buffer ts%3. Fills the barrier-skew window with store work.
        if (ts >= 2) {
            int bA = (ts - 2) % 3;
            int bB = (ts - 1) % 3;
            stream_out_plane(out, r, c0, ts - 2,
                             reinterpret_cast<const __half*>(staging3[bA]),
                             reinterpret_cast<const __half*>(staging3[bB]), tid);
        }

        __syncthreads();   // barrier 1: srows visible; early reads done

        // y-pool -> unscaled plane (fp16) into buffer ts%3
        if (w < 7) {
            #pragma unroll
            for (int xo = 0; xo < 7; ++xo) {
                float2 a  = srows[w][xo][l];
                float2 nb = srows[w + 1][xo][l];
                staging3[bufc][w * 7 + xo][l] =
                    __floats2half2_rn(a.x + nb.x, a.y + nb.y);
            }
        }

        __syncthreads();   // barrier 2: staging3[bufc] visible; srows free
        if (++bufc == 3) bufc = 0;
    }

    // epilogue: plane 3 = unscaled[3] (buf 0) + unscaled[4] (buf 1)
    stream_out_plane(out, r, c0, 3,
                     reinterpret_cast<const __half*>(staging3[0]),
                     reinterpret_cast<const __half*>(staging3[1]), tid);
}

// ---------------------------------------------------------------------------
extern "C" void kernel_launch(void* const* d_in, const int* in_sizes, int n_in,
                              void* d_out, int out_size) {
    const float* features = (const float*)d_in[0];
    const float* rois     = (const float*)d_in[1];
    float* out            = (float*)d_out;
    const int n_rois = in_sizes[1] / 7;

    dim3 tg(SPATIAL / 64, FT_C / 64, FT_B);
    transpose_kernel<<<tg, 256>>>(features);

    roialign_pool_kernel<<<dim3(n_rois, FT_C / CG), 256>>>(rois, out);
}

// round 17
// speedup vs baseline: 1.6731x; 1.4185x over previous
#include <cuda_runtime.h>
#include <cuda_fp16.h>

// Problem constants
#define FT_B 4
#define FT_C 256
#define FT_T 16
#define FT_H 64
#define FT_W 64
#define SPATIAL (FT_T*FT_H*FT_W)          // 65536 per (b,c)
#define FT_PER_B ((size_t)SPATIAL*FT_C)   // 16,777,216 elements per batch in fT

#define CG 64                              // channels per block (32 lanes x 2ch)

// Channels-last fp16 scratch: fT[b][t][h][w][c]  (134 MB static device array)
__device__ __half g_fT[(size_t)FT_B * FT_T * FT_H * FT_W * FT_C];

// ---------------------------------------------------------------------------
// Kernel 1: transpose (B,C,THW) f32 -> (B,THW,C) f16.
// 64x64 tiles; smem half tile with pitch 65 (conflict-free column reads);
// half2 STG (128 B/warp fully coalesced). At its 402 MB DRAM roofline.
// ---------------------------------------------------------------------------
__global__ __launch_bounds__(256, 6)
void transpose_kernel(const float* __restrict__ f) {
    __shared__ __half tile[64][65];
    const int b  = blockIdx.z;
    const int s0 = blockIdx.x * 64;   // spatial base
    const int c0 = blockIdx.y * 64;   // channel base
    const int tid = threadIdx.x;
    const int sx  = tid & 63;         // spatial within tile (coalesced reads)
    const int cyb = tid >> 6;         // 0..3

    const float* src = f + (size_t)b * FT_C * SPATIAL + s0 + sx;
    #pragma unroll
    for (int j = 0; j < 16; ++j) {
        int cy = cyb + j * 4;
        tile[cy][sx] = __float2half(src[(size_t)(c0 + cy) * SPATIAL]);
    }
    __syncthreads();

    // write: lane l covers channels 2l,2l+1; warp w handles 8 spatial rows
    const int l = tid & 31;
    const int w = tid >> 5;
    __half* dst = g_fT + (size_t)b * SPATIAL * FT_C + c0 + 2 * l;
    #pragma unroll
    for (int j = 0; j < 8; ++j) {
        int s = w + j * 8;
        __half2 v = __halves2half2(tile[2 * l][s], tile[2 * l + 1][s]);
        *reinterpret_cast<__half2*>(dst + (size_t)(s0 + s) * FT_C) = v;
    }
}

// ---------------------------------------------------------------------------
// Kernel 2: fused RoIAlign3D + avg_pool3d(k=2,s=1).  [CONVERGED CONFIG]
// Block = 8 warps x 32 lanes. warp = y-sample row, lane = channel PAIR
// (half2 gathers -> fp32 immediately; ALL math scalar fp32).
// grid = (n_rois, 4): roi varies fastest -> resident blocks share the same
// 64-channel slice (L2 resident). 6 CTAs/SM, regs 40, 2 plain barriers/iter.
// Proven-condemned alternatives (do NOT revisit): packed half2 math (R7/8),
// packed f32x2 math (R14), 32-bit combined-offset addressing (R11/12),
// forced 7 CTAs (R11) / 5-CTA fat-register (R9), named barriers (R15),
// triple-buffer early stream-out (R16).
// Addressing: four 64-bit corner POINTERS per ts.
// Interp: corner-major bilinear-(t,y) then x-lerp = 10 FFMA/channel.
// Pooled x-row streams through srows; staging planes fp16 (ts&1 double
// buffer, compile-time-constant bases); branch-free stream-out.
// ---------------------------------------------------------------------------
struct __align__(16) AxisEntry { int o0; int o1; float w0; float w1; };

__global__ __launch_bounds__(256, 6)
void roialign_pool_kernel(const float* __restrict__ rois,
                          float* __restrict__ out) {
    __shared__ AxisEntry sT[5], sY[8], sX[8];
    __shared__ float2  srows[8][7][32];      // [ysample][xout][lane]  14336 B
    __shared__ __half2 staging2h[2][49][33]; // [buf][pix][lanepair]   12936 B

    const int r   = blockIdx.x;             // roi (fastest-varying)
    const int g   = blockIdx.y;             // channel group 0..3
    const int tid = threadIdx.x;
    const int w   = tid >> 5;               // warp id = y-sample row
    const int l   = tid & 31;               // lane    = channel pair
    const float* roi = rois + r * 7;

    // --- axis sample tables (matches reference _axis_samples) ---
    if (tid < 21) {
        float start, end, fsize; int n, k, stride; AxisEntry* dstE;
        if (tid < 5)       { k = tid;      start = roi[5];          end = roi[6];          fsize = (float)FT_T; n = 5; stride = FT_H*FT_W*FT_C; dstE = &sT[k]; }
        else if (tid < 13) { k = tid - 5;  start = roi[2]*0.0625f;  end = roi[4]*0.0625f;  fsize = (float)FT_H; n = 8; stride = FT_W*FT_C;      dstE = &sY[k]; }
        else               { k = tid - 13; start = roi[1]*0.0625f;  end = roi[3]*0.0625f;  fsize = (float)FT_W; n = 8; stride = FT_C;           dstE = &sX[k]; }
        float length = fmaxf(end - start + 1.0f, 1.0f);
        float step   = length / (float)(n - 1);
        float coord  = start + step * (float)k;
        float valid  = (coord >= 0.0f && coord < fsize) ? 1.0f : 0.0f;
        float lo     = floorf(coord);
        lo = fminf(fmaxf(lo, 0.0f), fsize - 1.0f);
        float frac   = coord - lo;
        int loi = (int)lo;
        int hii = min(loi + 1, (int)fsize - 1);
        dstE->o0 = loi * stride;
        dstE->o1 = hii * stride;
        dstE->w0 = (1.0f - frac) * valid;
        dstE->w1 = frac * valid;
    }
    __syncthreads();

    const int b  = (int)roi[0];
    const int c0 = g * CG;
    const __half* bp = g_fT + (size_t)b * FT_PER_B + c0 + 2 * l;

    // this warp's y entry (fixed for all t)
    const int4  y4  = *reinterpret_cast<const int4*>(&sY[w]);
    const int   yO0 = y4.x, yO1 = y4.y;
    const float yW0 = __int_as_float(y4.z), yW1 = __int_as_float(y4.w);

    for (int ts = 0; ts < 5; ++ts) {
        const int buf = ts & 1;
        const int4  t4  = *reinterpret_cast<const int4*>(&sT[ts]);
        const int   tO0 = t4.x, tO1 = t4.y;
        const float tW0 = __int_as_float(t4.z), tW1 = __int_as_float(t4.w);

        // four 64-bit corner pointers (proven addressing -- keep!)
        const __half* p00 = bp + tO0 + yO0;
        const __half* p01 = bp + tO0 + yO1;
        const __half* p10 = bp + tO1 + yO0;
        const __half* p11 = bp + tO1 + yO1;
        const float w00 = tW0 * yW0, w01 = tW0 * yW1;
        const float w10 = tW1 * yW0, w11 = tW1 * yW1;

        // gather + fp32 interp (corner-major, 10 FFMA/ch) + x-pool -> srows
        float2 vprev;
        #pragma unroll
        for (int xs = 0; xs < 8; ++xs) {
            const int4  x4  = *reinterpret_cast<const int4*>(&sX[xs]);
            const int   xO0 = x4.x, xO1 = x4.y;
            const float xW0 = __int_as_float(x4.z), xW1 = __int_as_float(x4.w);

            float2 a0 = __half22float2(__ldg(reinterpret_cast<const __half2*>(p00 + xO0)));
            float2 a1 = __half22float2(__ldg(reinterpret_cast<const __half2*>(p00 + xO1)));
            float2 b0 = __half22float2(__ldg(reinterpret_cast<const __half2*>(p01 + xO0)));
            float2 b1 = __half22float2(__ldg(reinterpret_cast<const __half2*>(p01 + xO1)));
            float2 c0v = __half22float2(__ldg(reinterpret_cast<const __half2*>(p10 + xO0)));
            float2 c1v = __half22float2(__ldg(reinterpret_cast<const __half2*>(p10 + xO1)));
            float2 d0 = __half22float2(__ldg(reinterpret_cast<const __half2*>(p11 + xO0)));
            float2 d1 = __half22float2(__ldg(reinterpret_cast<const __half2*>(p11 + xO1)));

            // corner-major bilinear-in-(t,y), then lerp in x: 10 FFMA/channel
            float e0x = w00 * a0.x + w01 * b0.x + w10 * c0v.x + w11 * d0.x;
            float e1x = w00 * a1.x + w01 * b1.x + w10 * c1v.x + w11 * d1.x;
            float e0y = w00 * a0.y + w01 * b0.y + w10 * c0v.y + w11 * d0.y;
            float e1y = w00 * a1.y + w01 * b1.y + w10 * c1v.y + w11 * d1.y;

            float2 v;
            v.x = xW0 * e0x + xW1 * e1x;
            v.y = xW0 * e0y + xW1 * e1y;

            if (xs > 0) {
                float2 rp;
                rp.x = vprev.x + v.x;
                rp.y = vprev.y + v.y;
                srows[w][xs - 1][l] = rp;     // stream out, don't persist
            }
            vprev = v;
        }
        __syncthreads();   // srows visible (also: staging[buf] readers done)

        // y-pool reading BOTH rows from smem -> unscaled plane (fp16)
        if (w < 7) {
            #pragma unroll
            for (int xo = 0; xo < 7; ++xo) {
                float2 a  = srows[w][xo][l];
                float2 nb = srows[w + 1][xo][l];
                staging2h[buf][w * 7 + xo][l] =
                    __floats2half2_rn(a.x + nb.x, a.y + nb.y);
            }
        }
        __syncthreads();   // staging[buf] visible; srows readers done

        if (ts > 0) {
            // stream-out plane (ts-1) = (staging[0]+staging[1]) * 0.125
            const size_t obase = ((size_t)r * FT_C + c0) * 196 + (size_t)(ts - 1) * 49;
            const __half* sA = reinterpret_cast<const __half*>(staging2h[0]);
            const __half* sB = reinterpret_cast<const __half*>(staging2h[1]);
            // 3136 = 12*256 + 64 : branch-free body + small tail
            #pragma unroll
            for (int k = 0; k < 12; ++k) {
                int idx = tid + k * 256;
                int cc  = idx / 49;
                int pix = idx - cc * 49;
                float v = (__half2float(sA[pix * 66 + cc]) +
                           __half2float(sB[pix * 66 + cc])) * 0.125f;
                __stcs(&out[obase + (size_t)cc * 196 + pix], v);
            }
            if (tid < 64) {
                int idx = tid + 12 * 256;
                int cc  = idx / 49;
                int pix = idx - cc * 49;
                float v = (__half2float(sA[pix * 66 + cc]) +
                           __half2float(sB[pix * 66 + cc])) * 0.125f;
                __stcs(&out[obase + (size_t)cc * 196 + pix], v);
            }
        }
    }
}

// ---------------------------------------------------------------------------
extern "C" void kernel_launch(void* const* d_in, const int* in_sizes, int n_in,
                              void* d_out, int out_size) {
    const float* features = (const float*)d_in[0];
    const float* rois     = (const float*)d_in[1];
    float* out            = (float*)d_out;
    const int n_rois = in_sizes[1] / 7;

    dim3 tg(SPATIAL / 64, FT_C / 64, FT_B);
    transpose_kernel<<<tg, 256>>>(features);

    roialign_pool_kernel<<<dim3(n_rois, FT_C / CG), 256>>>(rois, out);
}